// round 4
// baseline (speedup 1.0000x reference)
#include <cuda_runtime.h>
#include <cstdint>

// Problem (fixed by reference):
//   x  : (2048, 16384) fp32   (B, Q*S)
//   W1 : (128, 128, 32) fp32  (Q, S, H)
//   b1 : (128, 32)
//   W2 : (128, 32, 1)
//   b2 : (128, 1)
//   out: (2048, 128) fp32     (B, Q)
#define Q_   128
#define S_   128
#define H_   32
#define C_   (Q_ * S_)
#define NB   256      // batches per block
#define SCH  64       // s rows staged per chunk
#define XPAD 260      // xs row stride (floats); 260*4B % 16B == 0 for LDS.128
#define THREADS 256

// packed fp32x2 FMA (Blackwell FFMA2): two independent IEEE fp32 FMAs per lane
__device__ __forceinline__ void fma_f32x2(unsigned long long& d,
                                          unsigned long long a,
                                          unsigned long long b,
                                          unsigned long long c) {
    asm("fma.rn.f32x2 %0, %1, %2, %3;" : "=l"(d) : "l"(a), "l"(b), "l"(c));
}
__device__ __forceinline__ unsigned long long pack2(float lo, float hi) {
    unsigned long long r;
    asm("mov.b64 %0, {%1, %2};" : "=l"(r) : "f"(lo), "f"(hi));
    return r;
}
__device__ __forceinline__ void unpack2(float& lo, float& hi, unsigned long long v) {
    asm("mov.b64 {%0, %1}, %2;" : "=f"(lo), "=f"(hi) : "l"(v));
}

__global__ __launch_bounds__(THREADS, 2)
void divenc_kernel(const float* __restrict__ x,
                   const float* __restrict__ W1,
                   const float* __restrict__ b1,
                   const float* __restrict__ W2,
                   const float* __restrict__ b2,
                   float* __restrict__ out)
{
    extern __shared__ float smem[];
    float* w1s = smem;                 // 4096 floats (16 KB)
    float* xs  = smem + S_ * H_;       // SCH*XPAD floats (~65 KB), layout [s][b]

    const int q   = blockIdx.y;
    const int b0  = blockIdx.x * NB;
    const int tid = threadIdx.x;
    const int warp = tid >> 5;
    const int lane = tid & 31;
    const int hg = warp >> 1;                    // 0..3 -> h = hg*8 + (0..7)
    const int bt = ((warp & 1) << 5) | lane;     // 0..63 -> b = bt*4 + (0..3)

    // ---- stage W1[q] (128x32) into smem, coalesced float4 ----
    {
        const float4* src = (const float4*)(W1 + (size_t)q * (S_ * H_));
        float4* dst = (float4*)w1s;
        #pragma unroll
        for (int i = tid; i < (S_ * H_) / 4; i += THREADS)
            dst[i] = src[i];
    }

    // 4 batches x 4 h-pairs of packed-f32x2 accumulators (32 fp32 accs)
    unsigned long long acc2[4][4];
    #pragma unroll
    for (int i = 0; i < 4; ++i)
        #pragma unroll
        for (int jp = 0; jp < 4; ++jp) acc2[i][jp] = 0ULL;

    const float* xrow = x + (size_t)(b0 + tid) * C_ + (size_t)q * S_;

    #pragma unroll
    for (int ch = 0; ch < S_ / SCH; ++ch) {
        __syncthreads();   // xs free (prev chunk fully read); orders w1s stage on ch==0

        // ---- stage x chunk transposed: xs[s][b]  (STS conflict-free: lane -> consecutive b) ----
        #pragma unroll
        for (int sc = 0; sc < SCH / 4; ++sc) {
            float4 v = *(const float4*)(xrow + ch * SCH + sc * 4);
            xs[(sc * 4 + 0) * XPAD + tid] = v.x;
            xs[(sc * 4 + 1) * XPAD + tid] = v.y;
            xs[(sc * 4 + 2) * XPAD + tid] = v.z;
            xs[(sc * 4 + 3) * XPAD + tid] = v.w;
        }
        __syncthreads();

        // ---- mainloop per s: 1 LDS.128 (x, conflict-free) + 2 LDS.128 (W, broadcast)
        //      + 4 broadcast packs + 16 fma.rn.f32x2  -> fma-pipe bound ----
        const float* wbase = w1s + ch * SCH * H_ + hg * 8;
        #pragma unroll 8
        for (int s = 0; s < SCH; ++s) {
            float4 xv = *(const float4*)(xs + s * XPAD + bt * 4);   // 4 batches
            unsigned long long w2p[4];
            {
                float4 wa = *(const float4*)(wbase + s * H_);       // h pairs: aligned reg pairs
                float4 wb = *(const float4*)(wbase + s * H_ + 4);
                w2p[0] = pack2(wa.x, wa.y);
                w2p[1] = pack2(wa.z, wa.w);
                w2p[2] = pack2(wb.x, wb.y);
                w2p[3] = pack2(wb.z, wb.w);
            }
            float xr[4] = {xv.x, xv.y, xv.z, xv.w};
            #pragma unroll
            for (int i = 0; i < 4; ++i) {
                unsigned long long x2 = pack2(xr[i], xr[i]);   // broadcast pack (real MOV)
                #pragma unroll
                for (int jp = 0; jp < 4; ++jp)
                    fma_f32x2(acc2[i][jp], x2, w2p[jp], acc2[i][jp]);
            }
        }
    }

    // ---- epilogue: + b1, ELU(alpha=1), dot with W2 over this thread's 8 h ----
    float part[4];
    {
        const float* b1q = b1 + q * H_ + hg * 8;
        const float* w2q = W2 + q * H_ + hg * 8;
        float b1v[8], w2v[8];
        #pragma unroll
        for (int j = 0; j < 8; ++j) { b1v[j] = b1q[j]; w2v[j] = w2q[j]; }
        #pragma unroll
        for (int i = 0; i < 4; ++i) {
            float a[8];
            #pragma unroll
            for (int jp = 0; jp < 4; ++jp)
                unpack2(a[2 * jp], a[2 * jp + 1], acc2[i][jp]);
            float sum = 0.0f;
            #pragma unroll
            for (int j = 0; j < 8; ++j) {
                float z = a[j] + b1v[j];
                float e = (z > 0.0f) ? z : expm1f(z);
                sum = fmaf(e, w2v[j], sum);
            }
            part[i] = sum;
        }
    }

    // ---- cross-warp reduction over the 4 h-groups ----
    __syncthreads();
    float* red = xs;   // reuse staging smem; needs 4*NB floats
    #pragma unroll
    for (int i = 0; i < 4; ++i)
        red[hg * NB + bt * 4 + i] = part[i];
    __syncthreads();

    const float bias2 = b2[q];
    float r = red[tid] + red[NB + tid] + red[2 * NB + tid] + red[3 * NB + tid] + bias2;
    out[(size_t)(b0 + tid) * Q_ + q] = r;
}

extern "C" void kernel_launch(void* const* d_in, const int* in_sizes, int n_in,
                              void* d_out, int out_size)
{
    const float* x  = (const float*)d_in[0];
    const float* W1 = (const float*)d_in[1];
    const float* b1 = (const float*)d_in[2];
    const float* W2 = (const float*)d_in[3];
    const float* b2 = (const float*)d_in[4];
    float* out = (float*)d_out;

    const int B = in_sizes[0] / C_;   // 2048
    const size_t smem_bytes = (size_t)(S_ * H_ + SCH * XPAD) * sizeof(float); // 82,944 B

    cudaFuncSetAttribute(divenc_kernel,
                         cudaFuncAttributeMaxDynamicSharedMemorySize,
                         (int)smem_bytes);

    dim3 grid(B / NB, Q_);
    divenc_kernel<<<grid, THREADS, smem_bytes>>>(x, W1, b1, W2, b2, out);
}

// round 15
// speedup vs baseline: 1.1212x; 1.1212x over previous
#include <cuda_runtime.h>
#include <cstdint>

// Problem (fixed by reference):
//   x  : (2048, 16384) fp32   (B, Q*S)
//   W1 : (128, 128, 32) fp32  (Q, S, H)
//   b1 : (128, 32),  W2 : (128, 32, 1),  b2 : (128, 1)
//   out: (2048, 128) fp32     (B, Q)
#define Q_   128
#define S_   128
#define H_   32
#define C_   (Q_ * S_)
#define NB   256            // batches per block
#define SCH  16             // s rows per pipeline stage
#define NCH  (S_ / SCH)     // 8 stages
#define XPAD 260            // xs row stride (floats); 16B-aligned strides
#define THREADS 256

// packed fp32x2 FMA (Blackwell FFMA2): two independent IEEE fp32 FMAs
__device__ __forceinline__ void fma_f32x2(unsigned long long& d,
                                          unsigned long long a,
                                          unsigned long long b,
                                          unsigned long long c) {
    asm("fma.rn.f32x2 %0, %1, %2, %3;" : "=l"(d) : "l"(a), "l"(b), "l"(c));
}
__device__ __forceinline__ unsigned long long pack2(float lo, float hi) {
    unsigned long long r;
    asm("mov.b64 %0, {%1, %2};" : "=l"(r) : "f"(lo), "f"(hi));
    return r;
}
__device__ __forceinline__ void unpack2(float& lo, float& hi, unsigned long long v) {
    asm("mov.b64 {%0, %1}, %2;" : "=f"(lo), "=f"(hi) : "l"(v));
}

__global__ __launch_bounds__(THREADS, 3)
void divenc_kernel(const float* __restrict__ x,
                   const float* __restrict__ W1,
                   const float* __restrict__ b1,
                   const float* __restrict__ W2,
                   const float* __restrict__ b2,
                   float* __restrict__ out)
{
    extern __shared__ float smem[];
    float* w1s = smem;                  // 4096 floats (16 KB)
    float* xs0 = smem + S_ * H_;        // 2 buffers of SCH*XPAD floats (~33 KB)

    const int q   = blockIdx.y;
    const int b0  = blockIdx.x * NB;
    const int tid = threadIdx.x;
    const int warp = tid >> 5;
    const int lane = tid & 31;
    const int hg = warp >> 1;                    // 0..3 -> h = hg*8 + (0..7)
    const int bt = ((warp & 1) << 5) | lane;     // 0..63 -> b = bt*4 + (0..3)

    // ---- stage W1[q] (128x32) into smem, coalesced float4 ----
    {
        const float4* src = (const float4*)(W1 + (size_t)q * (S_ * H_));
        float4* dst = (float4*)w1s;
        #pragma unroll
        for (int i = tid; i < (S_ * H_) / 4; i += THREADS)
            dst[i] = src[i];
    }

    // 4 batches x 4 h-pairs of packed-f32x2 accumulators (32 fp32 accs)
    unsigned long long acc2[4][4];
    #pragma unroll
    for (int i = 0; i < 4; ++i)
        #pragma unroll
        for (int jp = 0; jp < 4; ++jp) acc2[i][jp] = 0ULL;

    // each thread owns one batch row for staging
    const float4* xrow4 = (const float4*)(x + (size_t)(b0 + tid) * C_ + (size_t)q * S_);

    // ---- preload stage 0 into registers (4 x float4 = 16 floats) ----
    float4 A0 = xrow4[0], A1 = xrow4[1], A2 = xrow4[2], A3 = xrow4[3];

    #pragma unroll
    for (int ch = 0; ch < NCH; ++ch) {
        float* buf = xs0 + (ch & 1) * (SCH * XPAD);

        // ---- STS: transpose this thread's 16 staged floats into buf[s][b] ----
        // conflict-free: lanes -> consecutive b (word banks)
        buf[ 0 * XPAD + tid] = A0.x; buf[ 1 * XPAD + tid] = A0.y;
        buf[ 2 * XPAD + tid] = A0.z; buf[ 3 * XPAD + tid] = A0.w;
        buf[ 4 * XPAD + tid] = A1.x; buf[ 5 * XPAD + tid] = A1.y;
        buf[ 6 * XPAD + tid] = A1.z; buf[ 7 * XPAD + tid] = A1.w;
        buf[ 8 * XPAD + tid] = A2.x; buf[ 9 * XPAD + tid] = A2.y;
        buf[10 * XPAD + tid] = A2.z; buf[11 * XPAD + tid] = A2.w;
        buf[12 * XPAD + tid] = A3.x; buf[13 * XPAD + tid] = A3.y;
        buf[14 * XPAD + tid] = A3.z; buf[15 * XPAD + tid] = A3.w;

        // ---- prefetch next stage (overlaps with this stage's compute) ----
        if (ch + 1 < NCH) {
            const float4* p = xrow4 + (ch + 1) * (SCH / 4);
            A0 = p[0]; A1 = p[1]; A2 = p[2]; A3 = p[3];
        }

        __syncthreads();   // buf visible; also orders reuse (2-stage distance)

        // ---- compute SCH s-steps: per s = 1 LDS.128 (x) + 2 LDS.128 (W pairs,
        //      broadcast, loaded directly as u64 pairs) + 4 bcast packs
        //      + 16 fma.rn.f32x2  -> 23 issue slots / warp-s ----
        const float* wbase = w1s + (ch * SCH) * H_ + hg * 8;
        #pragma unroll
        for (int s = 0; s < SCH; ++s) {
            float4 xv = *(const float4*)(buf + s * XPAD + bt * 4);   // 4 batches
            // h-pairs contiguous & 16B-aligned: load packed pairs directly (no MOVs)
            ulonglong2 wpa = *(const ulonglong2*)(wbase + s * H_);
            ulonglong2 wpb = *(const ulonglong2*)(wbase + s * H_ + 4);
            unsigned long long w2p[4] = {wpa.x, wpa.y, wpb.x, wpb.y};
            float xr[4] = {xv.x, xv.y, xv.z, xv.w};
            #pragma unroll
            for (int i = 0; i < 4; ++i) {
                unsigned long long x2 = pack2(xr[i], xr[i]);         // broadcast pack
                #pragma unroll
                for (int jp = 0; jp < 4; ++jp)
                    fma_f32x2(acc2[i][jp], x2, w2p[jp], acc2[i][jp]);
            }
        }
        // no trailing barrier: next STS hits the other buffer; the sync at
        // iter ch+1 orders reuse of this one
    }

    // ---- epilogue: + b1, ELU(alpha=1), dot with W2 over this thread's 8 h ----
    float part[4];
    {
        const float* b1q = b1 + q * H_ + hg * 8;
        const float* w2q = W2 + q * H_ + hg * 8;
        float b1v[8], w2v[8];
        #pragma unroll
        for (int j = 0; j < 8; ++j) { b1v[j] = b1q[j]; w2v[j] = w2q[j]; }
        #pragma unroll
        for (int i = 0; i < 4; ++i) {
            float a[8];
            #pragma unroll
            for (int jp = 0; jp < 4; ++jp)
                unpack2(a[2 * jp], a[2 * jp + 1], acc2[i][jp]);
            float sum = 0.0f;
            #pragma unroll
            for (int j = 0; j < 8; ++j) {
                float z = a[j] + b1v[j];
                float e = (z > 0.0f) ? z : expm1f(z);
                sum = fmaf(e, w2v[j], sum);
            }
            part[i] = sum;
        }
    }

    // ---- cross-warp reduction over the 4 h-groups ----
    __syncthreads();   // all compute done before reusing xs
    float* red = xs0;  // needs 4*NB = 1024 floats
    #pragma unroll
    for (int i = 0; i < 4; ++i)
        red[hg * NB + bt * 4 + i] = part[i];
    __syncthreads();

    const float bias2 = b2[q];
    float r = red[tid] + red[NB + tid] + red[2 * NB + tid] + red[3 * NB + tid] + bias2;
    out[(size_t)(b0 + tid) * Q_ + q] = r;
}

extern "C" void kernel_launch(void* const* d_in, const int* in_sizes, int n_in,
                              void* d_out, int out_size)
{
    const float* x  = (const float*)d_in[0];
    const float* W1 = (const float*)d_in[1];
    const float* b1 = (const float*)d_in[2];
    const float* W2 = (const float*)d_in[3];
    const float* b2 = (const float*)d_in[4];
    float* out = (float*)d_out;

    const int B = in_sizes[0] / C_;   // 2048
    const size_t smem_bytes = (size_t)(S_ * H_ + 2 * SCH * XPAD) * sizeof(float); // 49,664 B

    cudaFuncSetAttribute(divenc_kernel,
                         cudaFuncAttributeMaxDynamicSharedMemorySize,
                         (int)smem_bytes);

    dim3 grid(B / NB, Q_);
    divenc_kernel<<<grid, THREADS, smem_bytes>>>(x, W1, b1, W2, b2, out);
}